// round 15
// baseline (speedup 1.0000x reference)
#include <cuda_runtime.h>
#include <cstdint>

// SpectralWindowPreprocessor: out[b,c,j,h,w] = x[b, reflect(c+j-3), h, w]
// B=4, C=31, J=7, H=W=512, reflect padding (mask all-ones) -> plane-gather copy.
//
// R13 fix: ptxas on sm_103a only accepts L2::evict_last on 256-bit loads
// (.v8.b32 / .v4.b64). So reads are now ld.global.nc.L2::evict_last.v4.b64
// (32 B each). Theory unchanged: pin the 130MB input in the 126MB L2 across
// the 7x reuse + graph replays, while the 910MB write stream stays
// evict-first (__stcs). Gather layout keeps ideal DRAM write locality
// (each CTA writes one contiguous plane segment).

static constexpr int C        = 31;
static constexpr int J        = 7;            // 2*3 + 1
static constexpr int HW32     = 32768;        // 512*512*4B / 32B chunks per plane
static constexpr int PLANES   = 4 * C * J;    // 868 output planes
static constexpr int TPB      = 256;
static constexpr int VPT      = 2;            // 32B chunks per thread (64 B total)

// 256-bit non-coherent load with L2 evict-last policy (pin input in L2).
__device__ __forceinline__ ulonglong4 ldg256_evict_last(const ulonglong4* p) {
    ulonglong4 v;
    asm("ld.global.nc.L2::evict_last.v4.b64 {%0, %1, %2, %3}, [%4];"
        : "=l"(v.x), "=l"(v.y), "=l"(v.z), "=l"(v.w)
        : "l"(p));
    return v;
}

// 32-byte evict-first streaming store as two 128-bit st.global.cs.
__device__ __forceinline__ void stg256_cs(ulonglong4* p, ulonglong4 v) {
    asm volatile("st.global.cs.v2.b64 [%0], {%1, %2};"
                 :: "l"(p), "l"(v.x), "l"(v.y) : "memory");
    asm volatile("st.global.cs.v2.b64 [%0], {%1, %2};"
                 :: "l"((char*)p + 16), "l"(v.z), "l"(v.w) : "memory");
}

__global__ __launch_bounds__(TPB)
void spectral_window_kernel(const ulonglong4* __restrict__ x,
                            ulonglong4* __restrict__ out) {
    const int plane = blockIdx.y;                 // ((b*C + c)*J + j)
    const int base  = (blockIdx.x * TPB) * VPT + threadIdx.x;

    const int j  = plane % J;
    const int bc = plane / J;                     // b*C + c
    const int c  = bc % C;
    const int b  = bc / C;

    // reflect padding: t = c + j - 3 mapped into [0, C)
    int t = c + j - 3;
    if (t < 0)       t = -t - 1;
    else if (t >= C) t = 2 * C - t - 1;

    const ulonglong4* src = x   + (size_t)(b * C + t) * HW32 + base;
    ulonglong4*       dst = out + (size_t)plane       * HW32 + base;

    // 2 independent 256-bit pinned-in-L2 loads (MLP=2 x 2 lines each),
    // then evict-first streaming stores. Stride TPB keeps accesses coalesced.
    ulonglong4 v0 = ldg256_evict_last(src + 0 * TPB);
    ulonglong4 v1 = ldg256_evict_last(src + 1 * TPB);
    stg256_cs(dst + 0 * TPB, v0);
    stg256_cs(dst + 1 * TPB, v1);
}

extern "C" void kernel_launch(void* const* d_in, const int* in_sizes, int n_in,
                              void* d_out, int out_size) {
    const ulonglong4* x   = (const ulonglong4*)d_in[0];
    ulonglong4*       out = (ulonglong4*)d_out;

    dim3 grid(HW32 / (TPB * VPT), PLANES, 1);   // (64, 868)
    spectral_window_kernel<<<grid, TPB>>>(x, out);
}

// round 16
// speedup vs baseline: 1.1276x; 1.1276x over previous
#include <cuda_runtime.h>
#include <cstdint>

// SpectralWindowPreprocessor: out[b,c,j,h,w] = x[b, reflect(c+j-3), h, w]
// B=4, C=31, J=7, H=W=512, reflect padding (mask all-ones) -> plane-gather copy.
//
// R15: back to the proven R5 shape (128-bit __ldg reads, __stcs writes,
// contiguous per-CTA write segments = best DRAM efficiency, 6.47 TB/s).
// evict_last pinning (R13) is abandoned: pinning 130MB into 126MB L2
// thrashes and collapsed DRAM to 4.3 TB/s. Change vs R5: VPT 4 -> 8
// (128 B/thread, MLP=8 front-batched LDGs, half the CTAs/index work).

static constexpr int C       = 31;
static constexpr int J       = 7;           // 2*3 + 1
static constexpr int HW_VEC  = 65536;       // 512*512/4 float4s per plane
static constexpr int PLANES  = 4 * C * J;   // 868 output planes
static constexpr int TPB     = 256;
static constexpr int VPT     = 8;           // float4s per thread (128 B)

__global__ __launch_bounds__(TPB)
void spectral_window_kernel(const float4* __restrict__ x,
                            float4* __restrict__ out) {
    const int plane = blockIdx.y;                 // ((b*C + c)*J + j)
    const int base  = (blockIdx.x * TPB) * VPT + threadIdx.x;

    const int j  = plane % J;
    const int bc = plane / J;                     // b*C + c
    const int c  = bc % C;
    const int b  = bc / C;

    // reflect padding: t = c + j - 3 mapped into [0, C)
    int t = c + j - 3;
    if (t < 0)       t = -t - 1;
    else if (t >= C) t = 2 * C - t - 1;

    const float4* src = x   + (size_t)(b * C + t) * HW_VEC + base;
    float4*       dst = out + (size_t)plane       * HW_VEC + base;

    // 8 independent 128-bit loads batched up front (MLP=8), then 8
    // evict-first streaming stores. Stride TPB keeps accesses coalesced.
    float4 v0 = __ldg(src + 0 * TPB);
    float4 v1 = __ldg(src + 1 * TPB);
    float4 v2 = __ldg(src + 2 * TPB);
    float4 v3 = __ldg(src + 3 * TPB);
    float4 v4 = __ldg(src + 4 * TPB);
    float4 v5 = __ldg(src + 5 * TPB);
    float4 v6 = __ldg(src + 6 * TPB);
    float4 v7 = __ldg(src + 7 * TPB);
    __stcs(dst + 0 * TPB, v0);
    __stcs(dst + 1 * TPB, v1);
    __stcs(dst + 2 * TPB, v2);
    __stcs(dst + 3 * TPB, v3);
    __stcs(dst + 4 * TPB, v4);
    __stcs(dst + 5 * TPB, v5);
    __stcs(dst + 6 * TPB, v6);
    __stcs(dst + 7 * TPB, v7);
}

extern "C" void kernel_launch(void* const* d_in, const int* in_sizes, int n_in,
                              void* d_out, int out_size) {
    const float4* x   = (const float4*)d_in[0];
    float4*       out = (float4*)d_out;

    dim3 grid(HW_VEC / (TPB * VPT), PLANES, 1);   // (32, 868)
    spectral_window_kernel<<<grid, TPB>>>(x, out);
}